// round 11
// baseline (speedup 1.0000x reference)
#include <cuda_runtime.h>
#include <cstdint>

#define N_ETA 7
#define FDIM 68
#define HW (512*1024)
#define CHUNK 512
#define NCH (HW / CHUNK)                 // 1024, exact
#define MAXSL 22
#define SLOTS (MAXSL*32)                 // 704
#define WSZ (N_ETA*FDIM*FDIM)            // 32368
#define TROWS 17                         // 68 = 4 * 17
#define TBUF (TROWS*CHUNK)               // 8704 floats
#define WROW 72                          // padded row: 2 segments of 36 floats

__device__ uint16_t g_sorted[NCH * SLOTS];
__device__ int g_nsl[NCH];

// ---------------- threefry2x32, key (0,42), jax partitionable path ----------------
__device__ __forceinline__ void threefry2x32_k42(uint32_t& x0, uint32_t& x1) {
    const uint32_t K2 = 0x1BD11BDAu ^ 0u ^ 42u;
#define TFR(r) { x0 += x1; x1 = __funnelshift_l(x1, x1, (r)); x1 ^= x0; }
    x1 += 42u;
    TFR(13) TFR(15) TFR(26) TFR(6)
    x0 += 42u;  x1 += K2 + 1u;
    TFR(17) TFR(29) TFR(16) TFR(24)
    x0 += K2;   x1 += 0u + 2u;
    TFR(13) TFR(15) TFR(26) TFR(6)
    x1 += 42u + 3u;
    TFR(17) TFR(29) TFR(16) TFR(24)
    x0 += 42u;  x1 += K2 + 4u;
    TFR(13) TFR(15) TFR(26) TFR(6)
    x0 += K2;   x1 += 0u + 5u;
#undef TFR
}

__device__ __forceinline__ float gumbel_from_bits(uint32_t bits) {
    float f = __uint_as_float((bits >> 9) | 0x3F800000u) - 1.0f;
    const float tiny = 1.1754943508222875e-38f;
    float u = fmaxf(tiny, f + tiny);
    return -logf(-logf(u));
}

// eta + chunk-local expert sort into padded 32-px groups.
// entry: bits[0:9)=local px, [9:12)=expert. Pads duplicate the expert's first
// real pixel (identical compute, identical store -> benign).
__global__ __launch_bounds__(CHUNK)
void eta_sort_kernel(const float* __restrict__ T, const int* __restrict__ eta) {
    __shared__ float logT[N_ETA * N_ETA];
    __shared__ uint16_t ent[SLOTS];
    __shared__ int hist[N_ETA], start[N_ETA + 1], cur[N_ETA];

    const int tid = threadIdx.x;
    const int c = blockIdx.x;
    const int cb = c * CHUNK;

    if (tid < N_ETA * N_ETA) logT[tid] = logf(T[tid] + 1e-9f);
    if (tid < N_ETA) hist[tid] = 0;
    for (int s = tid; s < SLOTS; s += CHUNK) ent[s] = 0xFFFFu;
    __syncthreads();

    int myE = 0;
    {
        int p = cb + tid;
        int r = eta[p] * N_ETA;
        float best = -3.0e38f;
#pragma unroll
        for (int k = 0; k < N_ETA; k++) {
            uint32_t x0 = 0u;
            uint32_t x1 = (uint32_t)(p * 7 + k);
            threefry2x32_k42(x0, x1);
            float v = logT[r + k] + gumbel_from_bits(x0 ^ x1);
            if (v > best) { best = v; myE = k; }
        }
        atomicAdd(&hist[myE], 1);
    }
    __syncthreads();
    if (tid == 0) {
        int s = 0;
        for (int e = 0; e < N_ETA; e++) { start[e] = s; cur[e] = s; s += (hist[e] + 31) & ~31; }
        start[N_ETA] = s;
        g_nsl[c] = s >> 5;
    }
    __syncthreads();
    {
        int pos = atomicAdd(&cur[myE], 1);
        ent[pos] = (uint16_t)(tid | (myE << 9));
    }
    __syncthreads();
    const int nsl32 = start[N_ETA];
    for (int s = tid; s < nsl32; s += CHUNK) {
        if (ent[s] == 0xFFFFu) {
            int e = 0;
#pragma unroll
            for (int k = 1; k < N_ETA; k++) if (s >= start[k]) e = k;
            ent[s] = ent[start[e]];
        }
    }
    __syncthreads();
    for (int s = tid; s < nsl32; s += CHUNK) g_sorted[c * SLOTS + s] = ent[s];
}

// ---------------- packed f32x2 + smem/async helpers ----------------
__device__ __forceinline__ unsigned long long pack_ff(float x, float y) {
    unsigned long long r;
    asm("mov.b64 %0, {%1, %2};" : "=l"(r) : "f"(x), "f"(y));
    return r;
}
__device__ __forceinline__ void unpack_ff(float& x, float& y, unsigned long long v) {
    asm("mov.b64 {%0, %1}, %2;" : "=f"(x), "=f"(y) : "l"(v));
}
__device__ __forceinline__ void fma2(unsigned long long& acc, unsigned long long w, unsigned long long v) {
    asm("fma.rn.f32x2 %0, %1, %2, %0;" : "+l"(acc) : "l"(w), "l"(v));
}
__device__ __forceinline__ void lds_v2u64(unsigned long long& a, unsigned long long& b, const float* p) {
    asm("ld.shared.v2.u64 {%0, %1}, [%2];"
        : "=l"(a), "=l"(b) : "l"(__cvta_generic_to_shared(p)));
}
__device__ __forceinline__ unsigned long long lds_u64(const float* p) {
    unsigned long long r;
    asm("ld.shared.u64 %0, [%1];" : "=l"(r) : "l"(__cvta_generic_to_shared(p)));
    return r;
}
__device__ __forceinline__ void cp_async16(float* dst_smem, const float* src_gmem) {
    asm volatile("cp.async.ca.shared.global [%0], [%1], 16;"
                 :: "r"((uint32_t)__cvta_generic_to_shared(dst_smem)), "l"(src_gmem));
}
#define CP_COMMIT()  asm volatile("cp.async.commit_group;" ::: "memory")
#define CP_WAIT(n)   asm volatile("cp.async.wait_group %0;" :: "n"(n) : "memory")

// Per 512-px chunk: warp = one 32-px same-expert slice.
// Lane split: t2 = lane>>4 owns o in [34*t2, 34*t2+34); g = lane&15 owns 2 px.
// W read as o-pair b64 vectors (no splats); feat splat 2x/f; acc = 34 b64.
__global__ __launch_bounds__(704, 1)
void compute_kernel(const float* __restrict__ feat, const float* __restrict__ W,
                    const float* __restrict__ b, float* __restrict__ out) {
    extern __shared__ float sh[];
    float* Wt  = sh;                 // 7*68*WROW  (per (e,f): 2 segments of 34 @ +0,+36)
    float* bs  = Wt + N_ETA * FDIM * WROW;   // 480
    float* buf = bs + 480;           // 2 * TBUF

    const int tid = threadIdx.x;
    const int lane = tid & 31, warp = tid >> 5;
    const int t2 = lane >> 4, g = lane & 15;

    // zero W region incl. pads, then stage
    for (int i = tid; i < N_ETA * FDIM * WROW; i += 704) Wt[i] = 0.f;
    __syncthreads();
    for (int i = tid; i < WSZ; i += 704) {
        int e = i / (FDIM * FDIM);
        int rem = i - e * (FDIM * FDIM);
        int o = rem / FDIM;
        int f = rem - o * FDIM;
        int seg = (o >= 34);
        int k = o - 34 * seg;
        Wt[(e * FDIM + f) * WROW + seg * 36 + k] = W[i];
    }
    for (int i = tid; i < N_ETA * FDIM; i += 704) bs[i] = b[i];
    __syncthreads();

    for (int c = blockIdx.x; c < NCH; c += gridDim.x) {
        const int cb = c * CHUNK;
        const int nsl = g_nsl[c];
        const bool active = (warp < nsl);

        int l0 = 0, l1 = 0, e = 0;
        if (active) {
            uint32_t e2 = *(const uint32_t*)(g_sorted + c * SLOTS + (warp << 5) + (g << 1));
            l0 = e2 & 0x1FF;
            l1 = (e2 >> 16) & 0x1FF;
            e = (e2 >> 9) & 7;
        }
        const float* wbase = Wt + (e * FDIM) * WROW + t2 * 36;
        const float* bp = bs + e * FDIM + t2 * 34;

        // acc[2j+p]: (out[t2*34+2j][px_p], out[t2*34+2j+1][px_p])
        unsigned long long acc[34];
        if (active) {
#pragma unroll
            for (int j = 0; j < 17; j++) {
                unsigned long long bb = lds_u64(bp + 2 * j);
                acc[2 * j] = bb;
                acc[2 * j + 1] = bb;
            }
        }

        // prologue: stage tile 0 (17 rows), shifts/masks only
        for (int i = tid; i < TROWS * 128; i += 704) {
            int row = i >> 7, col = (i & 127) << 2;
            cp_async16(buf + row * CHUNK + col, feat + (size_t)row * HW + cb + col);
        }
        CP_COMMIT();

        for (int t = 0; t < 4; t++) {
            if (t < 3) {
                const int f0 = (t + 1) * TROWS;
                float* dst = buf + ((t + 1) & 1) * TBUF;
                for (int i = tid; i < TROWS * 128; i += 704) {
                    int row = i >> 7, col = (i & 127) << 2;
                    cp_async16(dst + row * CHUNK + col, feat + (size_t)(f0 + row) * HW + cb + col);
                }
                CP_COMMIT();
                CP_WAIT(1);
            } else {
                CP_WAIT(0);
            }
            __syncthreads();
            if (active) {
                const float* B = buf + (t & 1) * TBUF;
                const float* wrow = wbase + (t * TROWS) * WROW;
#pragma unroll 1
                for (int fr = 0; fr < TROWS; fr++) {
                    const float* Brow = B + fr * CHUNK;
                    float v0 = Brow[l0];
                    float v1 = Brow[l1];
                    unsigned long long vv0 = pack_ff(v0, v0);
                    unsigned long long vv1 = pack_ff(v1, v1);
                    // exact mapping: load at +4*jj covers w floats [4jj,4jj+4)
                    // = o-pairs {2jj, 2jj+1} -> acc[4jj .. 4jj+3]
#pragma unroll
                    for (int jj = 0; jj < 8; jj++) {
                        unsigned long long wa, wb;
                        lds_v2u64(wa, wb, wrow + 4 * jj);
                        fma2(acc[4 * jj],     wa, vv0);
                        fma2(acc[4 * jj + 1], wa, vv1);
                        fma2(acc[4 * jj + 2], wb, vv0);
                        fma2(acc[4 * jj + 3], wb, vv1);
                    }
                    {
                        unsigned long long we = lds_u64(wrow + 32);  // o-pair 16
                        fma2(acc[32], we, vv0);
                        fma2(acc[33], we, vv1);
                    }
                    wrow += WROW;
                }
            }
            __syncthreads();
        }

        // epilogue: direct scattered STG within 2KB window (pads benign)
        if (active) {
            const int ob = t2 * 34;
            float* op0 = out + cb + l0;
            float* op1 = out + cb + l1;
#pragma unroll
            for (int j = 0; j < 17; j++) {
                float x, y;
                unpack_ff(x, y, acc[2 * j]);
                op0[(size_t)(ob + 2 * j) * HW] = x;
                op0[(size_t)(ob + 2 * j + 1) * HW] = y;
                unpack_ff(x, y, acc[2 * j + 1]);
                op1[(size_t)(ob + 2 * j) * HW] = x;
                op1[(size_t)(ob + 2 * j + 1) * HW] = y;
            }
        }
    }
}

extern "C" void kernel_launch(void* const* d_in, const int* in_sizes, int n_in,
                              void* d_out, int out_size) {
    const float* x   = 0;   // 35,651,584
    const float* W   = 0;   // 32,368
    const float* b   = 0;   // 476
    const float* T   = 0;   // 49
    const int*   eta = 0;   // 524,288
    for (int i = 0; i < n_in; i++) {
        switch (in_sizes[i]) {
            case 35651584: x   = (const float*)d_in[i]; break;
            case 32368:    W   = (const float*)d_in[i]; break;
            case 476:      b   = (const float*)d_in[i]; break;
            case 49:       T   = (const float*)d_in[i]; break;
            case 524288:   eta = (const int*)d_in[i];   break;
        }
    }
    float* out = (float*)d_out;

    eta_sort_kernel<<<NCH, CHUNK>>>(T, eta);

    int smem = (N_ETA * FDIM * WROW + 480 + 2 * TBUF) * (int)sizeof(float);   // 208,640 B
    cudaFuncSetAttribute(compute_kernel, cudaFuncAttributeMaxDynamicSharedMemorySize, smem);
    int dev = 0, sms = 148;
    cudaGetDevice(&dev);
    cudaDeviceGetAttribute(&sms, cudaDevAttrMultiProcessorCount, dev);
    compute_kernel<<<sms, 704, smem>>>(x, W, b, out);
}

// round 12
// speedup vs baseline: 4.1225x; 4.1225x over previous
#include <cuda_runtime.h>
#include <cstdint>

#define N_ETA 7
#define FDIM 68
#define HW (512*1024)
#define CHUNK 512
#define NCH (HW / CHUNK)          // 1024
#define SLOTS 544                 // 512 + 7*3 pad worst = 533 <= 544
#define THREADS 576               // 18 warps >= 17 worst-case slices
#define WSTRIDE 4628              // 68*68=4624 + 4;  4628 mod 32 = 20 -> e*20 distinct banks
#define TBUFW (17*SLOTS)          // 9248 floats per buffer

__device__ uint16_t g_sorted[NCH * SLOTS];
__device__ int g_nsl[NCH];

// ---------------- threefry2x32, key (0,42), jax partitionable path ----------------
__device__ __forceinline__ void threefry2x32_k42(uint32_t& x0, uint32_t& x1) {
    const uint32_t K2 = 0x1BD11BDAu ^ 0u ^ 42u;
#define TFR(r) { x0 += x1; x1 = __funnelshift_l(x1, x1, (r)); x1 ^= x0; }
    x1 += 42u;
    TFR(13) TFR(15) TFR(26) TFR(6)
    x0 += 42u;  x1 += K2 + 1u;
    TFR(17) TFR(29) TFR(16) TFR(24)
    x0 += K2;   x1 += 0u + 2u;
    TFR(13) TFR(15) TFR(26) TFR(6)
    x1 += 42u + 3u;
    TFR(17) TFR(29) TFR(16) TFR(24)
    x0 += 42u;  x1 += K2 + 4u;
    TFR(13) TFR(15) TFR(26) TFR(6)
    x0 += K2;   x1 += 0u + 5u;
#undef TFR
}

__device__ __forceinline__ float gumbel_from_bits(uint32_t bits) {
    float f = __uint_as_float((bits >> 9) | 0x3F800000u) - 1.0f;
    const float tiny = 1.1754943508222875e-38f;
    float u = fmaxf(tiny, f + tiny);
    return -logf(-logf(u));
}

// eta + chunk-local expert sort into groups PADDED TO 4.
// entry: bits[0:9)=local px, [9:12)=expert, [12]=valid.
// Pad slots copy the expert's first real entry with valid=0 (compute garbage, store masked).
__global__ __launch_bounds__(CHUNK)
void eta_sort_kernel(const float* __restrict__ T, const int* __restrict__ eta) {
    __shared__ float logT[N_ETA * N_ETA];
    __shared__ uint16_t ent[SLOTS];
    __shared__ int hist[N_ETA], start[N_ETA + 1], cur[N_ETA];

    const int tid = threadIdx.x;
    const int c = blockIdx.x;
    const int cb = c * CHUNK;

    if (tid < N_ETA * N_ETA) logT[tid] = logf(T[tid] + 1e-9f);
    if (tid < N_ETA) hist[tid] = 0;
    for (int s = tid; s < SLOTS; s += CHUNK) ent[s] = 0;
    __syncthreads();

    int myE = 0;
    {
        int p = cb + tid;
        int r = eta[p] * N_ETA;
        float best = -3.0e38f;
#pragma unroll
        for (int k = 0; k < N_ETA; k++) {
            uint32_t x0 = 0u;
            uint32_t x1 = (uint32_t)(p * 7 + k);
            threefry2x32_k42(x0, x1);
            float v = logT[r + k] + gumbel_from_bits(x0 ^ x1);
            if (v > best) { best = v; myE = k; }
        }
        atomicAdd(&hist[myE], 1);
    }
    __syncthreads();
    if (tid == 0) {
        int s = 0;
        for (int e = 0; e < N_ETA; e++) { start[e] = s; cur[e] = s; s += (hist[e] + 3) & ~3; }
        start[N_ETA] = s;                 // nslots <= 533
        g_nsl[c] = (s + 31) >> 5;         // slices <= 17
    }
    __syncthreads();
    {
        int pos = atomicAdd(&cur[myE], 1);
        ent[pos] = (uint16_t)(tid | (myE << 9) | (1 << 12));
    }
    __syncthreads();
    const int nslots = start[N_ETA];
    for (int s = tid; s < nslots; s += CHUNK) {
        if (ent[s] == 0) {
            int e = 0;
#pragma unroll
            for (int k = 1; k < N_ETA; k++) if (s >= start[k]) e = k;
            ent[s] = (uint16_t)(ent[start[e]] & 0x0FFF);   // valid=0
        }
    }
    __syncthreads();
    for (int s = tid; s < SLOTS; s += CHUNK) g_sorted[c * SLOTS + s] = ent[s];
}

// ---------------- packed f32x2 + smem/async helpers ----------------
__device__ __forceinline__ unsigned long long pack_ff(float x, float y) {
    unsigned long long r;
    asm("mov.b64 %0, {%1, %2};" : "=l"(r) : "f"(x), "f"(y));
    return r;
}
__device__ __forceinline__ void unpack_ff(float& x, float& y, unsigned long long v) {
    asm("mov.b64 {%0, %1}, %2;" : "=f"(x), "=f"(y) : "l"(v));
}
__device__ __forceinline__ void fma2(unsigned long long& acc, unsigned long long w, unsigned long long v) {
    asm("fma.rn.f32x2 %0, %1, %2, %0;" : "+l"(acc) : "l"(w), "l"(v));
}
__device__ __forceinline__ unsigned long long lds_u64(const float* p) {
    unsigned long long r;
    asm("ld.shared.u64 %0, [%1];" : "=l"(r) : "l"(__cvta_generic_to_shared(p)));
    return r;
}
__device__ __forceinline__ void cp_async4(float* dst_smem, const float* src_gmem) {
    asm volatile("cp.async.ca.shared.global [%0], [%1], 4;"
                 :: "r"((uint32_t)__cvta_generic_to_shared(dst_smem)), "l"(src_gmem));
}
#define CP_COMMIT()  asm volatile("cp.async.commit_group;" ::: "memory")
#define CP_WAIT(n)   asm volatile("cp.async.wait_group %0;" :: "n"(n) : "memory")

// Per 512-px chunk: warp = one 32-slot slice; lane = (team t2 = lane>>3 owning
// o in [17*t2, 17*t2+17)) x (group g = lane&7 owning 4 same-expert pixels).
// Each W word loaded once per lane feeds 4 pixels (2 fma2). feat lands in smem
// PRE-PERMUTED via 4-byte cp.async scatter, so pixel quads are contiguous u64 pairs.
__global__ __launch_bounds__(THREADS, 1)
void compute_kernel(const float* __restrict__ feat, const float* __restrict__ W,
                    const float* __restrict__ b, float* __restrict__ out) {
    extern __shared__ float sh[];
    float* Wt   = sh;                          // 7 * WSTRIDE, layout [e][f][o]
    float* bs   = Wt + N_ETA * WSTRIDE;        // 480
    float* bufP = bs + 480;                    // 2 * TBUFW (permuted feat tiles)
    uint16_t* o2s = (uint16_t*)(bufP + 2 * TBUFW);   // 544

    const int tid = threadIdx.x;
    const int lane = tid & 31, warp = tid >> 5;
    const int g = lane & 7, t2 = lane >> 3;
    const int tbase = t2 * 17;

    // stage W transposed: Wt[e*WSTRIDE + f*68 + o] = W[e][o][f]; pads never read
    for (int i = tid; i < N_ETA * FDIM * FDIM; i += THREADS) {
        int e = i / (FDIM * FDIM);
        int rem = i - e * (FDIM * FDIM);
        int o = rem / FDIM;
        int f = rem - o * FDIM;
        Wt[e * WSTRIDE + f * FDIM + o] = W[i];
    }
    for (int i = tid; i < N_ETA * FDIM; i += THREADS) bs[i] = b[i];
    __syncthreads();

    for (int c = blockIdx.x; c < NCH; c += gridDim.x) {
        const int cb = c * CHUNK;
        const int nsl = g_nsl[c];
        __syncthreads();                         // prior chunk fully consumed
        for (int s = tid; s < SLOTS; s += THREADS) {
            uint16_t en = g_sorted[c * SLOTS + s];
            if (en & (1 << 12)) o2s[en & 511] = (uint16_t)s;
        }
        __syncthreads();

        const bool active = (warp < nsl);
        unsigned long long ents = 0;
        if (active)
            ents = *(const unsigned long long*)(g_sorted + c * SLOTS + (warp << 5) + (g << 2));
        const int e = (int)((ents >> 9) & 7);
        const float* wbase = Wt + e * WSTRIDE + tbase;
        const int slotbase = (warp << 5) + (g << 2);

        // acc[2j] = (px0,px1), acc[2j+1] = (px2,px3) for o = tbase + j
        unsigned long long acc[34];
        if (active) {
            const float* bp = bs + e * FDIM + tbase;
#pragma unroll
            for (int j = 0; j < 17; j++) {
                float bv = bp[j];
                unsigned long long bb = pack_ff(bv, bv);
                acc[2 * j] = bb;
                acc[2 * j + 1] = bb;
            }
        }

        // prologue: stage tile 0 permuted (coalesced gmem read, 4B smem scatter)
        for (int i = tid; i < 17 * CHUNK; i += THREADS) {
            int fl = i >> 9, px = i & 511;
            cp_async4(bufP + fl * SLOTS + o2s[px], feat + (size_t)fl * HW + cb + px);
        }
        CP_COMMIT();

        for (int t = 0; t < 4; t++) {
            if (t < 3) {
                const int f0 = (t + 1) * 17;
                float* dst = bufP + ((t + 1) & 1) * TBUFW;
                for (int i = tid; i < 17 * CHUNK; i += THREADS) {
                    int fl = i >> 9, px = i & 511;
                    cp_async4(dst + fl * SLOTS + o2s[px], feat + (size_t)(f0 + fl) * HW + cb + px);
                }
                CP_COMMIT();
                CP_WAIT(1);
            } else {
                CP_WAIT(0);
            }
            __syncthreads();
            if (active) {
                const float* B = bufP + (t & 1) * TBUFW + slotbase;
                const float* wrow = wbase + (t * 17) * FDIM;
#pragma unroll 1
                for (int fl = 0; fl < 17; fl++) {
                    unsigned long long v01 = lds_u64(B + fl * SLOTS);
                    unsigned long long v23 = lds_u64(B + fl * SLOTS + 2);
#pragma unroll
                    for (int j = 0; j < 17; j++) {
                        float w = wrow[j];
                        unsigned long long ww = pack_ff(w, w);
                        fma2(acc[2 * j],     ww, v01);
                        fma2(acc[2 * j + 1], ww, v23);
                    }
                    wrow += FDIM;
                }
            }
            __syncthreads();
        }

        // epilogue: validity-masked scattered STG within the 2KB chunk window
        if (active) {
            const int l0 = (int)(ents & 511),          va0 = (int)((ents >> 12) & 1);
            const int l1 = (int)((ents >> 16) & 511),  va1 = (int)((ents >> 28) & 1);
            const int l2 = (int)((ents >> 32) & 511),  va2 = (int)((ents >> 44) & 1);
            const int l3 = (int)((ents >> 48) & 511),  va3 = (int)((ents >> 60) & 1);
            float* rowp = out + (size_t)tbase * HW + cb;
#pragma unroll
            for (int j = 0; j < 17; j++) {
                float x, y;
                unpack_ff(x, y, acc[2 * j]);
                if (va0) rowp[l0] = x;
                if (va1) rowp[l1] = y;
                unpack_ff(x, y, acc[2 * j + 1]);
                if (va2) rowp[l2] = x;
                if (va3) rowp[l3] = y;
                rowp += HW;
            }
        }
    }
}

extern "C" void kernel_launch(void* const* d_in, const int* in_sizes, int n_in,
                              void* d_out, int out_size) {
    const float* x   = 0;   // 35,651,584
    const float* W   = 0;   // 32,368
    const float* b   = 0;   // 476
    const float* T   = 0;   // 49
    const int*   eta = 0;   // 524,288
    for (int i = 0; i < n_in; i++) {
        switch (in_sizes[i]) {
            case 35651584: x   = (const float*)d_in[i]; break;
            case 32368:    W   = (const float*)d_in[i]; break;
            case 476:      b   = (const float*)d_in[i]; break;
            case 49:       T   = (const float*)d_in[i]; break;
            case 524288:   eta = (const int*)d_in[i];   break;
        }
    }
    float* out = (float*)d_out;

    eta_sort_kernel<<<NCH, CHUNK>>>(T, eta);

    int smem = (N_ETA * WSTRIDE + 480 + 2 * TBUFW) * (int)sizeof(float)
             + SLOTS * (int)sizeof(uint16_t);          // ~206.6 KB
    cudaFuncSetAttribute(compute_kernel, cudaFuncAttributeMaxDynamicSharedMemorySize, smem);
    int dev = 0, sms = 148;
    cudaGetDevice(&dev);
    cudaDeviceGetAttribute(&sms, cudaDevAttrMultiProcessorCount, dev);
    compute_kernel<<<sms, THREADS, smem>>>(x, W, b, out);
}